// round 15
// baseline (speedup 1.0000x reference)
#include <cuda_runtime.h>
#include <cstdint>
#include <math.h>
#include <float.h>

#define NB 4096
#define TT 200
#define DD 64
#define H1 16
#define H2 8
#define TILE_FLOATS (TT * DD)            // 12800
#define TILE_BYTES  (TILE_FLOATS * 4)    // 51200
#define NTILES 13

#define NEG_INF_F (-4294967296.0f)

__device__ __forceinline__ void cp_async16(uint32_t smem_dst, const void* gsrc) {
    asm volatile("cp.async.cg.shared.global [%0], [%1], 16;\n"
                 :: "r"(smem_dst), "l"(gsrc));
}
#define CP_COMMIT() asm volatile("cp.async.commit_group;\n" ::: "memory")
#define CP_WAIT1()  asm volatile("cp.async.wait_group 1;\n" ::: "memory")

__device__ __forceinline__ float fsigmoid(float x) {
    float t;
    asm("tanh.approx.f32 %0, %1;" : "=f"(t) : "f"(x * 0.5f));
    return fmaf(t, 0.5f, 0.5f);
}
__device__ __forceinline__ void mma_tf32(float& d0, float& d1, float& d2, float& d3,
                                         uint32_t a0, uint32_t a1, uint32_t a2, uint32_t a3,
                                         uint32_t b0, uint32_t b1) {
    asm volatile("mma.sync.aligned.m16n8k8.row.col.f32.tf32.tf32.f32 "
                 "{%0,%1,%2,%3}, {%4,%5,%6,%7}, {%8,%9}, {%0,%1,%2,%3};"
                 : "+f"(d0), "+f"(d1), "+f"(d2), "+f"(d3)
                 : "r"(a0), "r"(a1), "r"(a2), "r"(a3), "r"(b0), "r"(b1));
}

__device__ __forceinline__ void copy_tile(uint32_t sbase, const float* __restrict__ kg,
                                          int bb, int tid)
{
    const char* gp = (const char*)(kg + (size_t)bb * TILE_FLOATS);
    #pragma unroll
    for (int it = 0; it < 12; it++) {               // 12*256 = 3072
        int i = tid + it * 256;
        int t = i >> 4, c = i & 15;
        cp_async16(sbase + t * 256 + ((c ^ (t & 15)) << 4), gp + i * 16);
    }
    if (tid < 128) {                                 // remaining 128
        int i = tid + 3072;
        int t = i >> 4, c = i & 15;
        cp_async16(sbase + t * 256 + ((c ^ (t & 15)) << 4), gp + i * 16);
    }
}

__global__ __launch_bounds__(256, 2)
void din_attn_kernel(const float* __restrict__ qg,
                     const float* __restrict__ kg,
                     const int*   __restrict__ lg,
                     const float* __restrict__ W1,
                     const float* __restrict__ b1,
                     const float* __restrict__ W2,
                     const float* __restrict__ b2,
                     const float* __restrict__ W3,
                     const float* __restrict__ b3,
                     const float* __restrict__ W4,
                     const float* __restrict__ b4,
                     float* __restrict__ outg)
{
    extern __shared__ float k_s[];                  // 2 swizzled tiles, 102400 B
    __shared__ __align__(16) float U[1536];         // M -> sc/op/o scratch
    __shared__ float v_s[H1];
    __shared__ float W2_s[H1 * H2];
    __shared__ float b2_s[H2];
    __shared__ float W3_s[H2];
    __shared__ float red_s[8];
    __shared__ float b3_s;

    const int tid  = threadIdx.x;
    const int wid  = tid >> 5;       // 0..7
    const int lane = tid & 31;
    const int g    = lane >> 2;
    const int j    = lane & 3;
    const uint32_t sb = (uint32_t)__cvta_generic_to_shared(k_s);

    // ---- prologue: first tile + constant params ----
    copy_tile(sb, kg, blockIdx.x, tid);
    CP_COMMIT();
    if (tid < H1 * H2) W2_s[tid] = W2[tid];
    if (tid >= 128 && tid < 128 + H2) { b2_s[tid - 128] = b2[tid - 128]; W3_s[tid - 128] = W3[tid - 128]; }
    if (tid == 255) b3_s = b3[0];
    __syncthreads();

    float w2r[4][H2];
    {
        int rows[4] = {2 * j, 2 * j + 1, 8 + 2 * j, 8 + 2 * j + 1};
        #pragma unroll
        for (int rr = 0; rr < 4; rr++)
            #pragma unroll
            for (int kk = 0; kk < H2; kk++) w2r[rr][kk] = W2_s[rows[rr] * H2 + kk];
    }

    int cur = 0;
    for (int b = blockIdx.x; b < NB; b += gridDim.x) {
        // ---- prefetch next batch tile ----
        int bn = b + gridDim.x;
        if (bn < NB) copy_tile(sb + (cur ^ 1) * TILE_BYTES, kg, bn, tid);
        CP_COMMIT();                                 // always (maybe empty group)

        // ---- per-batch M into U + v ----
        const float* qrow = qg + (size_t)b * DD;
        #pragma unroll
        for (int it = 0; it < 4; it++) {             // 4*256 = 1024
            int i = tid + it * 256;
            int d = i >> 4, h = i & 15;
            U[i] = W1[(64 + d) * H1 + h] - W1[(128 + d) * H1 + h]
                 + qrow[d] * W1[(192 + d) * H1 + h];
        }
        if (tid < H1) {
            float a0 = 0.f, a1 = 0.f;
            #pragma unroll 8
            for (int d = 0; d < DD; d += 2) {
                a0 = fmaf(qrow[d + 0], W1[(d + 0) * H1 + tid] + W1[(128 + d + 0) * H1 + tid], a0);
                a1 = fmaf(qrow[d + 1], W1[(d + 1) * H1 + tid] + W1[(128 + d + 1) * H1 + tid], a1);
            }
            v_s[tid] = b1[tid] + a0 + a1;
        }
        const int len = lg[b];
        __syncthreads();                             // M + v visible

        // ---- B fragments (fp32 bits -> tf32 truncation) ----
        uint32_t bf[8][2][2];
        #pragma unroll
        for (int kc = 0; kc < 8; kc++) {
            #pragma unroll
            for (int nh = 0; nh < 2; nh++) {
                bf[kc][nh][0] = __float_as_uint(U[(kc * 8 + j)     * H1 + nh * 8 + g]);
                bf[kc][nh][1] = __float_as_uint(U[(kc * 8 + j + 4) * H1 + nh * 8 + g]);
            }
        }
        const float vA0 = v_s[2 * j],     vA1 = v_s[2 * j + 1];
        const float vB0 = v_s[8 + 2 * j], vB1 = v_s[8 + 2 * j + 1];

        CP_WAIT1();                                  // current tile done (next in flight)
        __syncthreads();                             // tile visible; U free

        float* sc_s = U;                             // [200]
        float* op_s = U + 256;                       // [16][64]
        float* o_s  = U + 1280;                      // [64]
        const uint32_t* ku = reinterpret_cast<const uint32_t*>(k_s + cur * TILE_FLOATS);

        // ---- pass 1: tiles over 8 warps ----
        for (int tile = wid; tile < NTILES; tile += 8) {
            const int tA = tile * 16 + g;
            const int tB = tA + 8;
            const int ra = (tA < TT) ? tA : (TT - 1);
            const int rb = (tB < TT) ? tB : (TT - 1);
            const int xa = ra & 15, xb = rb & 15;
            const uint32_t baseA = ra * 64 + j;
            const uint32_t baseB = rb * 64 + j;

            float c00 = 0.f, c01 = 0.f, c02 = 0.f, c03 = 0.f;
            float c10 = 0.f, c11 = 0.f, c12 = 0.f, c13 = 0.f;

            #pragma unroll
            for (int kc = 0; kc < 8; kc++) {
                uint32_t a0 = ku[baseA + (((2 * kc)     ^ xa) << 2)];
                uint32_t a1 = ku[baseB + (((2 * kc)     ^ xb) << 2)];
                uint32_t a2 = ku[baseA + (((2 * kc + 1) ^ xa) << 2)];
                uint32_t a3 = ku[baseB + (((2 * kc + 1) ^ xb) << 2)];
                mma_tf32(c00, c01, c02, c03, a0, a1, a2, a3, bf[kc][0][0], bf[kc][0][1]);
                mma_tf32(c10, c11, c12, c13, a0, a1, a2, a3, bf[kc][1][0], bf[kc][1][1]);
            }

            float hA0 = fsigmoid(c00 + vA0), hA1 = fsigmoid(c01 + vA1);
            float hA2 = fsigmoid(c10 + vB0), hA3 = fsigmoid(c11 + vB1);
            float hB0 = fsigmoid(c02 + vA0), hB1 = fsigmoid(c03 + vA1);
            float hB2 = fsigmoid(c12 + vB0), hB3 = fsigmoid(c13 + vB1);

            float pA[H2], pB[H2];
            #pragma unroll
            for (int kk = 0; kk < H2; kk++) {
                pA[kk] = hA0 * w2r[0][kk] + hA1 * w2r[1][kk]
                       + hA2 * w2r[2][kk] + hA3 * w2r[3][kk];
                pB[kk] = hB0 * w2r[0][kk] + hB1 * w2r[1][kk]
                       + hB2 * w2r[2][kk] + hB3 * w2r[3][kk];
            }
            #pragma unroll
            for (int off = 1; off <= 2; off <<= 1) {
                #pragma unroll
                for (int kk = 0; kk < H2; kk++) {
                    pA[kk] += __shfl_xor_sync(0xffffffffu, pA[kk], off);
                    pB[kk] += __shfl_xor_sync(0xffffffffu, pB[kk], off);
                }
            }
            float scA = b3_s, scB = b3_s;
            #pragma unroll
            for (int kk = 0; kk < H2; kk++) {
                scA = fmaf(fsigmoid(pA[kk] + b2_s[kk]), W3_s[kk], scA);
                scB = fmaf(fsigmoid(pB[kk] + b2_s[kk]), W3_s[kk], scB);
            }
            if (j == 0) {
                if (tA < TT) sc_s[tA] = ((tA < len) ? scA : NEG_INF_F) * 0.125f;
                if (tB < TT) sc_s[tB] = ((tB < len) ? scB : NEG_INF_F) * 0.125f;
            }
        }
        __syncthreads();

        // ---- softmax max ----
        float s = (tid < TT) ? sc_s[tid] : -FLT_MAX;
        float val = s;
        #pragma unroll
        for (int o = 16; o; o >>= 1) val = fmaxf(val, __shfl_xor_sync(0xffffffffu, val, o));
        if (lane == 0) red_s[wid] = val;
        __syncthreads();
        float mx = red_s[0];
        #pragma unroll
        for (int i = 1; i < 8; i++) mx = fmaxf(mx, red_s[i]);
        __syncthreads();

        // ---- exp + sum ----
        float p = 0.0f;
        if (tid < TT) { p = __expf(s - mx); sc_s[tid] = p; }
        #pragma unroll
        for (int o = 16; o; o >>= 1) p += __shfl_xor_sync(0xffffffffu, p, o);
        if (lane == 0) red_s[wid] = p;
        __syncthreads();
        float denom = 0.f;
        #pragma unroll
        for (int i = 0; i < 8; i++) denom += red_s[i];
        float inv = __fdividef(1.0f, denom);

        // ---- pass 2: 256 threads = 16 t-groups x 16 d-quads ----
        {
            int gg = tid >> 4, dq = tid & 15;
            int tb = gg * 13;                        // 16*13 = 208, guard < 200
            float4 acc = make_float4(0.f, 0.f, 0.f, 0.f);
            const float4* k4 = reinterpret_cast<const float4*>(k_s + cur * TILE_FLOATS);
            #pragma unroll
            for (int i = 0; i < 13; i++) {
                int t = tb + i;
                if (t < TT) {
                    float w = sc_s[t];
                    float4 kv = k4[t * 16 + (dq ^ (t & 15))];
                    acc.x = fmaf(w, kv.x, acc.x);
                    acc.y = fmaf(w, kv.y, acc.y);
                    acc.z = fmaf(w, kv.z, acc.z);
                    acc.w = fmaf(w, kv.w, acc.w);
                }
            }
            *reinterpret_cast<float4*>(op_s + gg * 64 + dq * 4) = acc;
        }
        __syncthreads();
        if (tid < DD) {
            float sum = 0.f;
            #pragma unroll
            for (int gg = 0; gg < 16; gg++) sum += op_s[gg * 64 + tid];
            o_s[tid] = sum * inv;
        }
        __syncthreads();

        // ---- projection: 4 groups x 64 d, 16 dp each ----
        {
            int gg = tid >> 6, d = tid & 63;
            int dp0 = gg * 16;
            float a0 = 0.f, a1 = 0.f;
            #pragma unroll
            for (int dp = 0; dp < 16; dp += 2) {
                a0 = fmaf(o_s[dp0 + dp],     W4[(dp0 + dp)     * DD + d], a0);
                a1 = fmaf(o_s[dp0 + dp + 1], W4[(dp0 + dp + 1) * DD + d], a1);
            }
            op_s[gg * 64 + d] = a0 + a1;
        }
        __syncthreads();
        if (tid < DD)
            outg[(size_t)b * DD + tid] =
                (op_s[tid] + op_s[64 + tid]) + (op_s[128 + tid] + op_s[192 + tid]) + b4[tid];
        __syncthreads();                             // protect U + tile before next iter

        cur ^= 1;
    }
}

extern "C" void kernel_launch(void* const* d_in, const int* in_sizes, int n_in,
                              void* d_out, int out_size)
{
    const float* q  = (const float*)d_in[0];
    const float* k  = (const float*)d_in[1];
    const int*   l  = (const int*)d_in[2];
    const float* W1 = (const float*)d_in[3];
    const float* b1 = (const float*)d_in[4];
    const float* W2 = (const float*)d_in[5];
    const float* b2 = (const float*)d_in[6];
    const float* W3 = (const float*)d_in[7];
    const float* b3 = (const float*)d_in[8];
    const float* W4 = (const float*)d_in[9];
    const float* b4 = (const float*)d_in[10];
    float* out = (float*)d_out;

    int dev = 0;
    cudaGetDevice(&dev);
    int sms = 0;
    cudaDeviceGetAttribute(&sms, cudaDevAttrMultiProcessorCount, dev);
    if (sms <= 0) sms = 148;
    int grid = sms * 2;
    if (grid > NB) grid = NB;

    const int smem_bytes = 2 * TILE_BYTES;           // 102400 B dynamic
    cudaFuncSetAttribute(din_attn_kernel,
                         cudaFuncAttributeMaxDynamicSharedMemorySize, smem_bytes);

    din_attn_kernel<<<grid, 256, smem_bytes>>>(q, k, l, W1, b1, W2, b2,
                                               W3, b3, W4, b4, out);
}

// round 16
// speedup vs baseline: 1.3998x; 1.3998x over previous
#include <cuda_runtime.h>
#include <cstdint>
#include <math.h>
#include <float.h>

#define NB 4096
#define TT 200
#define DD 64
#define H1 16
#define H2 8
#define TILE_FLOATS (TT * DD)            // 12800
#define TILE_BYTES  (TILE_FLOATS * 4)    // 51200
#define NTILES 13                        // 13*16 = 208 >= 200 rows

#define NEG_INF_F (-4294967296.0f)

__device__ __forceinline__ void cp_async16(uint32_t smem_dst, const void* gsrc) {
    asm volatile("cp.async.cg.shared.global [%0], [%1], 16;\n"
                 :: "r"(smem_dst), "l"(gsrc));
}
__device__ __forceinline__ void cp_async_wait_all() {
    asm volatile("cp.async.wait_all;\n" ::: "memory");
}
// sigmoid via tanh.approx: 1 MUFU + 2 flops
__device__ __forceinline__ float fsigmoid(float x) {
    float t;
    asm("tanh.approx.f32 %0, %1;" : "=f"(t) : "f"(x * 0.5f));
    return fmaf(t, 0.5f, 0.5f);
}
__device__ __forceinline__ void mma_tf32(float& d0, float& d1, float& d2, float& d3,
                                         uint32_t a0, uint32_t a1, uint32_t a2, uint32_t a3,
                                         uint32_t b0, uint32_t b1) {
    asm volatile("mma.sync.aligned.m16n8k8.row.col.f32.tf32.tf32.f32 "
                 "{%0,%1,%2,%3}, {%4,%5,%6,%7}, {%8,%9}, {%0,%1,%2,%3};"
                 : "+f"(d0), "+f"(d1), "+f"(d2), "+f"(d3)
                 : "r"(a0), "r"(a1), "r"(a2), "r"(a3), "r"(b0), "r"(b1));
}

__global__ __launch_bounds__(128, 4)
void din_attn_kernel(const float* __restrict__ qg,
                     const float* __restrict__ kg,
                     const int*   __restrict__ lg,
                     const float* __restrict__ W1,
                     const float* __restrict__ b1,
                     const float* __restrict__ W2,
                     const float* __restrict__ b2,
                     const float* __restrict__ W3,
                     const float* __restrict__ b3,
                     const float* __restrict__ W4,
                     const float* __restrict__ b4,
                     float* __restrict__ outg)
{
    extern __shared__ float k_s[];                  // dense swizzled tile, 51200 B
    __shared__ __align__(16) float U[1024];         // M (B-preload) -> exp/op/o
    __shared__ float v_s[H1];
    __shared__ float W2_s[H1 * H2];
    __shared__ float b2_s[H2];
    __shared__ float W3_s[H2];
    __shared__ float red_s[8];
    __shared__ float b3_s;
    __shared__ float bd_s;                          // static softmax bound

    const int b    = blockIdx.x;
    const int tid  = threadIdx.x;
    const int wid  = tid >> 5;
    const int lane = tid & 31;
    const int g    = lane >> 2;     // 0..7  (fragment row group)
    const int j    = lane & 3;      // 0..3  (fragment col group)
    const uint32_t sb = (uint32_t)__cvta_generic_to_shared(k_s);

    // ---- issue ALL key-tile copies asynchronously (XOR-quad swizzle) ----
    {
        const char* gp = (const char*)(kg + (size_t)b * TILE_FLOATS);
        #pragma unroll
        for (int it = 0; it < 25; it++) {           // 25*128 = 3200 float4s exactly
            int i = tid + it * 128;
            int t = i >> 4, c = i & 15;
            cp_async16(sb + t * 256 + ((c ^ (t & 15)) << 4), gp + i * 16);
        }
    }

    // ---- tiny parameter loads (overlap with async copies) ----
    W2_s[tid] = W2[tid];                            // 128 elements, 128 threads
    if (tid < H2) { b2_s[tid] = b2[tid]; W3_s[tid] = W3[tid]; }
    if (tid == 127) {
        float b3v = b3[0];
        float asum = 0.f;
        #pragma unroll
        for (int kk = 0; kk < H2; kk++) asum += fabsf(W3[kk]);
        b3_s = b3v;
        bd_s = 0.125f * (b3v + asum);               // >= any valid scaled score
    }

    // ---- M[d][h] = W1b - W1c + q_d * W1d  (into U; q via L1-cached LDG) ----
    const float* qrow = qg + (size_t)b * DD;
    #pragma unroll
    for (int it = 0; it < 8; it++) {                // 8*128 = 1024
        int i = tid + it * 128;
        int d = i >> 4, h = i & 15;
        U[i] = W1[(64 + d) * H1 + h] - W1[(128 + d) * H1 + h]
             + qrow[d] * W1[(192 + d) * H1 + h];
    }
    // ---- v[h] = b1 + q @ (W1a + W1c) ----
    if (tid < H1) {
        float a0 = 0.f, a1 = 0.f;
        #pragma unroll 8
        for (int d = 0; d < DD; d += 2) {
            a0 = fmaf(qrow[d + 0], W1[(d + 0) * H1 + tid] + W1[(128 + d + 0) * H1 + tid], a0);
            a1 = fmaf(qrow[d + 1], W1[(d + 1) * H1 + tid] + W1[(128 + d + 1) * H1 + tid], a1);
        }
        v_s[tid] = b1[tid] + a0 + a1;
    }

    const int len = lg[b];

    cp_async_wait_all();
    __syncthreads();                                // tile + M + params ready

    // ---- preload B fragments (raw fp32 bits -> tf32 truncation) + W2 rows ----
    uint32_t bf[8][2][2];                           // [k-chunk][n-half][reg]
    #pragma unroll
    for (int kc = 0; kc < 8; kc++) {
        #pragma unroll
        for (int nh = 0; nh < 2; nh++) {
            bf[kc][nh][0] = __float_as_uint(U[(kc * 8 + j)     * H1 + nh * 8 + g]);
            bf[kc][nh][1] = __float_as_uint(U[(kc * 8 + j + 4) * H1 + nh * 8 + g]);
        }
    }
    float w2r[4][H2];                               // W2 rows 2j, 2j+1, 8+2j, 8+2j+1
    {
        int rows[4] = {2 * j, 2 * j + 1, 8 + 2 * j, 8 + 2 * j + 1};
        #pragma unroll
        for (int rr = 0; rr < 4; rr++) {
            #pragma unroll
            for (int kk = 0; kk < H2; kk++) w2r[rr][kk] = W2_s[rows[rr] * H2 + kk];
        }
    }
    const float vA0 = v_s[2 * j],     vA1 = v_s[2 * j + 1];
    const float vB0 = v_s[8 + 2 * j], vB1 = v_s[8 + 2 * j + 1];
    const float bd    = bd_s;
    const float zfill = (len == 0) ? 1.0f : 0.0f;   // len==0 -> uniform softmax

    __syncthreads();                                // M reads done; U reusable

    float* sc_s = U;           // [200] exp values (unnormalized)
    float* op_s = U + 256;     // [8][64]
    float* o_s  = U + 768;     // [64]

    const uint32_t* ku = reinterpret_cast<const uint32_t*>(k_s);

    // ---- pass 1: tf32 mma scorer + tail MLP + exp, warp w: tiles w, w+4, ... ----
    for (int tile = wid; tile < NTILES; tile += 4) {
        const int tA = tile * 16 + g;               // true rows
        const int tB = tA + 8;
        const int ra = (tA < TT) ? tA : (TT - 1);   // clamped for smem addressing
        const int rb = (tB < TT) ? tB : (TT - 1);
        const int xa = ra & 15, xb = rb & 15;
        const uint32_t baseA = ra * 64 + j;
        const uint32_t baseB = rb * 64 + j;

        float c00 = 0.f, c01 = 0.f, c02 = 0.f, c03 = 0.f;   // n-half 0
        float c10 = 0.f, c11 = 0.f, c12 = 0.f, c13 = 0.f;   // n-half 1

        #pragma unroll
        for (int kc = 0; kc < 8; kc++) {
            uint32_t a0 = ku[baseA + (((2 * kc)     ^ xa) << 2)];
            uint32_t a1 = ku[baseB + (((2 * kc)     ^ xb) << 2)];
            uint32_t a2 = ku[baseA + (((2 * kc + 1) ^ xa) << 2)];
            uint32_t a3 = ku[baseB + (((2 * kc + 1) ^ xb) << 2)];
            mma_tf32(c00, c01, c02, c03, a0, a1, a2, a3, bf[kc][0][0], bf[kc][0][1]);
            mma_tf32(c10, c11, c12, c13, a0, a1, a2, a3, bf[kc][1][0], bf[kc][1][1]);
        }

        float hA0 = fsigmoid(c00 + vA0), hA1 = fsigmoid(c01 + vA1);
        float hA2 = fsigmoid(c10 + vB0), hA3 = fsigmoid(c11 + vB1);
        float hB0 = fsigmoid(c02 + vA0), hB1 = fsigmoid(c03 + vA1);
        float hB2 = fsigmoid(c12 + vB0), hB3 = fsigmoid(c13 + vB1);

        float pA[H2], pB[H2];
        #pragma unroll
        for (int kk = 0; kk < H2; kk++) {
            pA[kk] = hA0 * w2r[0][kk] + hA1 * w2r[1][kk]
                   + hA2 * w2r[2][kk] + hA3 * w2r[3][kk];
            pB[kk] = hB0 * w2r[0][kk] + hB1 * w2r[1][kk]
                   + hB2 * w2r[2][kk] + hB3 * w2r[3][kk];
        }
        #pragma unroll
        for (int off = 1; off <= 2; off <<= 1) {
            #pragma unroll
            for (int kk = 0; kk < H2; kk++) {
                pA[kk] += __shfl_xor_sync(0xffffffffu, pA[kk], off);
                pB[kk] += __shfl_xor_sync(0xffffffffu, pB[kk], off);
            }
        }
        float scA = b3_s, scB = b3_s;
        #pragma unroll
        for (int kk = 0; kk < H2; kk++) {
            scA = fmaf(fsigmoid(pA[kk] + b2_s[kk]), W3_s[kk], scA);
            scB = fmaf(fsigmoid(pB[kk] + b2_s[kk]), W3_s[kk], scB);
        }
        if (j == 0) {
            // exp(score*0.125 - bd): bd >= any valid score ⇒ result in (0,1]
            if (tA < TT) sc_s[tA] = (tA < len) ? __expf(fmaf(scA, 0.125f, -bd)) : zfill;
            if (tB < TT) sc_s[tB] = (tB < len) ? __expf(fmaf(scB, 0.125f, -bd)) : zfill;
        }
    }
    __syncthreads();                                // all exp values in sc_s

    const float4* k4 = reinterpret_cast<const float4*>(k_s);

    // ---- pass 2: weighted key sum + denominator partials ----
    {
        int gg = tid >> 4, dq = tid & 15;
        int tb = gg * 25;
        float4 acc = make_float4(0.f, 0.f, 0.f, 0.f);
        float ws = 0.f;
        #pragma unroll 5
        for (int i = 0; i < 25; i++) {
            int t = tb + i;
            float w = sc_s[t];
            float4 kv = k4[t * 16 + (dq ^ (t & 15))];
            ws += w;
            acc.x = fmaf(w, kv.x, acc.x);
            acc.y = fmaf(w, kv.y, acc.y);
            acc.z = fmaf(w, kv.z, acc.z);
            acc.w = fmaf(w, kv.w, acc.w);
        }
        *reinterpret_cast<float4*>(op_s + gg * 64 + dq * 4) = acc;
        if (dq == 0) red_s[gg] = ws;                // denominator partial per t-group
    }
    __syncthreads();
    if (tid < DD) {
        float sum = 0.f;
        #pragma unroll
        for (int gg = 0; gg < 8; gg++) sum += op_s[gg * 64 + tid];
        float denom = ((red_s[0] + red_s[1]) + (red_s[2] + red_s[3]))
                    + ((red_s[4] + red_s[5]) + (red_s[6] + red_s[7]));
        o_s[tid] = sum * __fdividef(1.0f, denom);
    }
    __syncthreads();

    // ---- projection partials: thread (gg,d), gg in {0,1}, sums 32 dp each ----
    {
        int gg = tid >> 6, d = tid & 63;
        int dp0 = gg * 32;
        float a0 = 0.f, a1 = 0.f;
        #pragma unroll 8
        for (int dp = 0; dp < 32; dp += 2) {
            a0 = fmaf(o_s[dp0 + dp],     W4[(dp0 + dp)     * DD + d], a0);
            a1 = fmaf(o_s[dp0 + dp + 1], W4[(dp0 + dp + 1) * DD + d], a1);
        }
        op_s[gg * 64 + d] = a0 + a1;
    }
    __syncthreads();
    if (tid < DD)
        outg[(size_t)b * DD + tid] = op_s[tid] + op_s[64 + tid] + b4[tid];
}

extern "C" void kernel_launch(void* const* d_in, const int* in_sizes, int n_in,
                              void* d_out, int out_size)
{
    const float* q  = (const float*)d_in[0];
    const float* k  = (const float*)d_in[1];
    const int*   l  = (const int*)d_in[2];
    const float* W1 = (const float*)d_in[3];
    const float* b1 = (const float*)d_in[4];
    const float* W2 = (const float*)d_in[5];
    const float* b2 = (const float*)d_in[6];
    const float* W3 = (const float*)d_in[7];
    const float* b3 = (const float*)d_in[8];
    const float* W4 = (const float*)d_in[9];
    const float* b4 = (const float*)d_in[10];
    float* out = (float*)d_out;

    const int smem_bytes = TILE_BYTES;   // 51200 B dynamic
    cudaFuncSetAttribute(din_attn_kernel,
                         cudaFuncAttributeMaxDynamicSharedMemorySize, smem_bytes);

    din_attn_kernel<<<NB, 128, smem_bytes>>>(q, k, l, W1, b1, W2, b2,
                                             W3, b3, W4, b4, out);
}

// round 17
// speedup vs baseline: 1.6964x; 1.2119x over previous
#include <cuda_runtime.h>
#include <cstdint>
#include <math.h>
#include <float.h>

#define NB 4096
#define TT 200
#define DD 64
#define H1 16
#define H2 8
#define TILE_FLOATS (TT * DD)            // 12800
#define NTILES 13                        // 13*16 = 208 >= 200 rows
#define RING 8                           // ring chunks (16 rows, 4KB each)

__device__ __forceinline__ void cp_async16(uint32_t smem_dst, const void* gsrc) {
    asm volatile("cp.async.cg.shared.global [%0], [%1], 16;\n"
                 :: "r"(smem_dst), "l"(gsrc));
}
#define CP_COMMIT() asm volatile("cp.async.commit_group;\n" ::: "memory")
#define CP_WAIT(n)  asm volatile("cp.async.wait_group %0;\n" :: "n"(n) : "memory")

__device__ __forceinline__ float fsigmoid(float x) {
    float t;
    asm("tanh.approx.f32 %0, %1;" : "=f"(t) : "f"(x * 0.5f));
    return fmaf(t, 0.5f, 0.5f);
}
__device__ __forceinline__ void mma_tf32(float& d0, float& d1, float& d2, float& d3,
                                         uint32_t a0, uint32_t a1, uint32_t a2, uint32_t a3,
                                         uint32_t b0, uint32_t b1) {
    asm volatile("mma.sync.aligned.m16n8k8.row.col.f32.tf32.tf32.f32 "
                 "{%0,%1,%2,%3}, {%4,%5,%6,%7}, {%8,%9}, {%0,%1,%2,%3};"
                 : "+f"(d0), "+f"(d1), "+f"(d2), "+f"(d3)
                 : "r"(a0), "r"(a1), "r"(a2), "r"(a3), "r"(b0), "r"(b1));
}

// copy chunk p (rows 16p..16p+15; chunk 12 has 8 rows) into ring slot p&7
__device__ __forceinline__ void copy_chunk(uint32_t sb, const char* gp, int p, int tid) {
    const int nf4 = (p == 12) ? 128 : 256;
    const uint32_t slotbase = sb + (uint32_t)(p & 7) * 4096;
    #pragma unroll
    for (int i0 = 0; i0 < 256; i0 += 128) {
        int i = tid + i0;
        if (i < nf4) {
            int rr = i >> 4, c = i & 15;
            cp_async16(slotbase + rr * 256 + ((c ^ rr) << 4),
                       gp + (size_t)(16 * p + rr) * 256 + c * 16);
        }
    }
}

__global__ __launch_bounds__(128, 5)
void din_attn_kernel(const float* __restrict__ qg,
                     const float* __restrict__ kg,
                     const int*   __restrict__ lg,
                     const float* __restrict__ W1,
                     const float* __restrict__ b1,
                     const float* __restrict__ W2,
                     const float* __restrict__ b2,
                     const float* __restrict__ W3,
                     const float* __restrict__ b3,
                     const float* __restrict__ W4,
                     const float* __restrict__ b4,
                     float* __restrict__ outg)
{
    extern __shared__ float k_s[];                  // ring: 8 chunks * 4KB = 32768 B
    __shared__ __align__(16) float U[1024];         // M (bf preload) -> op/o scratch
    __shared__ float v_s[H1];
    __shared__ float W2_s[H1 * H2];
    __shared__ float b2_s[H2];
    __shared__ float W3_s[H2];
    __shared__ float red_s[4];
    __shared__ float b3_s;
    __shared__ float bd_s;                          // static softmax bound

    const int b    = blockIdx.x;
    const int tid  = threadIdx.x;
    const int wid  = tid >> 5;
    const int lane = tid & 31;
    const int g    = lane >> 2;     // 0..7
    const int j    = lane & 3;      // 0..3
    const uint32_t sb = (uint32_t)__cvta_generic_to_shared(k_s);
    const char* gp = (const char*)(kg + (size_t)b * TILE_FLOATS);

    // ---- issue first 8 chunks, one commit group each ----
    #pragma unroll
    for (int p = 0; p < 8; p++) { copy_chunk(sb, gp, p, tid); CP_COMMIT(); }

    // ---- params (overlap with copies) ----
    W2_s[tid] = W2[tid];
    if (tid < H2) { b2_s[tid] = b2[tid]; W3_s[tid] = W3[tid]; }
    if (tid == 127) {
        float b3v = b3[0];
        float asum = 0.f;
        #pragma unroll
        for (int kk = 0; kk < H2; kk++) asum += fabsf(W3[kk]);
        b3_s = b3v;
        bd_s = 0.125f * (b3v + asum);
    }

    // ---- M[d][h] = W1b - W1c + q_d * W1d  (into U) ----
    const float* qrow = qg + (size_t)b * DD;
    #pragma unroll
    for (int it = 0; it < 8; it++) {
        int i = tid + it * 128;
        int d = i >> 4, h = i & 15;
        U[i] = W1[(64 + d) * H1 + h] - W1[(128 + d) * H1 + h]
             + qrow[d] * W1[(192 + d) * H1 + h];
    }
    if (tid < H1) {
        float a0 = 0.f, a1 = 0.f;
        #pragma unroll 8
        for (int d = 0; d < DD; d += 2) {
            a0 = fmaf(qrow[d + 0], W1[(d + 0) * H1 + tid] + W1[(128 + d + 0) * H1 + tid], a0);
            a1 = fmaf(qrow[d + 1], W1[(d + 1) * H1 + tid] + W1[(128 + d + 1) * H1 + tid], a1);
        }
        v_s[tid] = b1[tid] + a0 + a1;
    }
    const int len = lg[b];
    __syncthreads();                                // M + v + params visible

    // ---- B fragments (fp32 bits -> tf32 truncation) ----
    uint32_t bf[8][2][2];
    #pragma unroll
    for (int kc = 0; kc < 8; kc++) {
        #pragma unroll
        for (int nh = 0; nh < 2; nh++) {
            bf[kc][nh][0] = __float_as_uint(U[(kc * 8 + j)     * H1 + nh * 8 + g]);
            bf[kc][nh][1] = __float_as_uint(U[(kc * 8 + j + 4) * H1 + nh * 8 + g]);
        }
    }
    const float vA0 = v_s[2 * j],     vA1 = v_s[2 * j + 1];
    const float vB0 = v_s[8 + 2 * j], vB1 = v_s[8 + 2 * j + 1];
    const float bd    = bd_s;
    const float zfill = (len == 0) ? 1.0f : 0.0f;

    const uint32_t* ku = reinterpret_cast<const uint32_t*>(k_s);

    float oax = 0.f, oay = 0.f, dn = 0.f;           // per-lane output partials

    // ---- per-tile: mma scorer + tail MLP + exp + fused weighted accumulate ----
    auto do_tile = [&](int tile) {
        const uint32_t sbase = (uint32_t)(tile & 7) * 1024;   // float index
        const int xa = g, xb = g + 8;               // row-in-chunk = swizzle key
        const uint32_t baseA = sbase + (uint32_t)g * 64 + j;
        const uint32_t baseB = sbase + (uint32_t)(g + 8) * 64 + j;

        float c00 = 0.f, c01 = 0.f, c02 = 0.f, c03 = 0.f;
        float c10 = 0.f, c11 = 0.f, c12 = 0.f, c13 = 0.f;
        #pragma unroll
        for (int kc = 0; kc < 8; kc++) {
            uint32_t a0 = ku[baseA + (((2 * kc)     ^ xa) << 2)];
            uint32_t a1 = ku[baseB + (((2 * kc)     ^ xb) << 2)];
            uint32_t a2 = ku[baseA + (((2 * kc + 1) ^ xa) << 2)];
            uint32_t a3 = ku[baseB + (((2 * kc + 1) ^ xb) << 2)];
            mma_tf32(c00, c01, c02, c03, a0, a1, a2, a3, bf[kc][0][0], bf[kc][0][1]);
            mma_tf32(c10, c11, c12, c13, a0, a1, a2, a3, bf[kc][1][0], bf[kc][1][1]);
        }

        float hA0 = fsigmoid(c00 + vA0), hA1 = fsigmoid(c01 + vA1);
        float hA2 = fsigmoid(c10 + vB0), hA3 = fsigmoid(c11 + vB1);
        float hB0 = fsigmoid(c02 + vA0), hB1 = fsigmoid(c03 + vA1);
        float hB2 = fsigmoid(c12 + vB0), hB3 = fsigmoid(c13 + vB1);

        float pA[H2], pB[H2];
        #pragma unroll
        for (int kk = 0; kk < H2; kk++) {
            pA[kk] = hA0 * W2_s[(2 * j)     * H2 + kk] + hA1 * W2_s[(2 * j + 1) * H2 + kk]
                   + hA2 * W2_s[(8 + 2 * j) * H2 + kk] + hA3 * W2_s[(9 + 2 * j) * H2 + kk];
            pB[kk] = hB0 * W2_s[(2 * j)     * H2 + kk] + hB1 * W2_s[(2 * j + 1) * H2 + kk]
                   + hB2 * W2_s[(8 + 2 * j) * H2 + kk] + hB3 * W2_s[(9 + 2 * j) * H2 + kk];
        }
        #pragma unroll
        for (int off = 1; off <= 2; off <<= 1) {
            #pragma unroll
            for (int kk = 0; kk < H2; kk++) {
                pA[kk] += __shfl_xor_sync(0xffffffffu, pA[kk], off);
                pB[kk] += __shfl_xor_sync(0xffffffffu, pB[kk], off);
            }
        }
        float scA = b3_s, scB = b3_s;
        #pragma unroll
        for (int kk = 0; kk < H2; kk++) {
            scA = fmaf(fsigmoid(pA[kk] + b2_s[kk]), W3_s[kk], scA);
            scB = fmaf(fsigmoid(pB[kk] + b2_s[kk]), W3_s[kk], scB);
        }
        const int tA = tile * 16 + g;               // always < 200
        const int tB = tA + 8;                      // >= 200 only for tile 12
        float eA = (tA < len) ? __expf(fmaf(scA, 0.125f, -bd)) : zfill;
        float eB = (tB >= TT) ? 0.f
                 : ((tB < len) ? __expf(fmaf(scB, 0.125f, -bd)) : zfill);

        // fused weighted key sum: lane owns cols {2*lane, 2*lane+1}
        const uint32_t abase = sbase + ((uint32_t)(lane >> 1) << 2) + (lane & 1) * 2;
        #pragma unroll
        for (int r = 0; r < 16; r++) {
            float w = __shfl_sync(0xffffffffu, (r < 8) ? eA : eB, (r & 7) * 4);
            const float2 k2 = *reinterpret_cast<const float2*>(
                k_s + (abase ^ (r << 2)) + r * 64);
            oax = fmaf(w, k2.x, oax);
            oay = fmaf(w, k2.y, oay);
            dn += w;
        }
    };

    // ---- phases: staged on per-chunk commit groups ----
    CP_WAIT(4); __syncthreads();                    // chunks 0..3 resident
    do_tile(wid);
    __syncthreads();                                // slots 0..3 free
    #pragma unroll
    for (int p = 8; p < 12; p++) { copy_chunk(sb, gp, p, tid); CP_COMMIT(); }

    CP_WAIT(4); __syncthreads();                    // chunks 4..7 resident
    do_tile(4 + wid);
    __syncthreads();                                // slot 4 free
    copy_chunk(sb, gp, 12, tid); CP_COMMIT();

    CP_WAIT(1); __syncthreads();                    // chunks 8..11 resident
    do_tile(8 + wid);
    __syncthreads();

    CP_WAIT(0); __syncthreads();                    // chunk 12 resident
    if (wid == 0) do_tile(12);
    __syncthreads();                                // all partials done; U free

    // ---- combine warp partials ----
    float* op_s = U;            // [4][64]
    float* o_s  = U + 256;      // [64]
    *reinterpret_cast<float2*>(op_s + wid * 64 + lane * 2) = make_float2(oax, oay);
    if (lane == 0) red_s[wid] = dn;
    __syncthreads();
    if (tid < DD) {
        float sum = (op_s[tid] + op_s[64 + tid]) + (op_s[128 + tid] + op_s[192 + tid]);
        float denom = (red_s[0] + red_s[1]) + (red_s[2] + red_s[3]);
        o_s[tid] = sum * __fdividef(1.0f, denom);
    }
    __syncthreads();

    // ---- projection: thread (gg,d), gg in {0,1}, sums 32 dp each ----
    {
        int gg = tid >> 6, d = tid & 63;
        int dp0 = gg * 32;
        float a0 = 0.f, a1 = 0.f;
        #pragma unroll 8
        for (int dp = 0; dp < 32; dp += 2) {
            a0 = fmaf(o_s[dp0 + dp],     W4[(dp0 + dp)     * DD + d], a0);
            a1 = fmaf(o_s[dp0 + dp + 1], W4[(dp0 + dp + 1) * DD + d], a1);
        }
        op_s[gg * 64 + d] = a0 + a1;
    }
    __syncthreads();
    if (tid < DD)
        outg[(size_t)b * DD + tid] = op_s[tid] + op_s[64 + tid] + b4[tid];
}

extern "C" void kernel_launch(void* const* d_in, const int* in_sizes, int n_in,
                              void* d_out, int out_size)
{
    const float* q  = (const float*)d_in[0];
    const float* k  = (const float*)d_in[1];
    const int*   l  = (const int*)d_in[2];
    const float* W1 = (const float*)d_in[3];
    const float* b1 = (const float*)d_in[4];
    const float* W2 = (const float*)d_in[5];
    const float* b2 = (const float*)d_in[6];
    const float* W3 = (const float*)d_in[7];
    const float* b3 = (const float*)d_in[8];
    const float* W4 = (const float*)d_in[9];
    const float* b4 = (const float*)d_in[10];
    float* out = (float*)d_out;

    const int smem_bytes = RING * 4096;  // 32768 B dynamic
    cudaFuncSetAttribute(din_attn_kernel,
                         cudaFuncAttributeMaxDynamicSharedMemorySize, smem_bytes);

    din_attn_kernel<<<NB, 128, smem_bytes>>>(q, k, l, W1, b1, W2, b2,
                                             W3, b3, W4, b4, out);
}